// round 14
// baseline (speedup 1.0000x reference)
#include <cuda_runtime.h>
#include <math.h>

#define NLOC 1940
#define NPRI 8732
#define BATCH 16
#define TOPK 10
#define NOBJ (BATCH*TOPK)
#define DS 64
#define IMG 300
#define ZWHAT 64
#define CPAD 4
#define TILE 16
#define NTX ((IMG + TILE - 1) / TILE)   // 19

typedef unsigned long long ull;

// ---------------- device scratch (no allocation allowed) -------------------
__device__ __align__(16) float g_decoded[NOBJ * CPAD * DS * DS];   // 10.5 MB
__device__ int   g_order[BATCH * TOPK];

// ---------------- f32x2 helpers --------------------------------------------
__device__ __forceinline__ ull pack2(float lo, float hi) {
    ull r; asm("mov.b64 %0, {%1, %2};" : "=l"(r) : "f"(lo), "f"(hi)); return r;
}
__device__ __forceinline__ void unpack2(ull v, float& a, float& b) {
    asm("mov.b64 {%0, %1}, %2;" : "=f"(a), "=f"(b) : "l"(v));
}
__device__ __forceinline__ ull ffma2(ull a, ull b, ull c) {
    ull d; asm("fma.rn.f32x2 %0, %1, %2, %3;" : "=l"(d) : "l"(a), "l"(b), "l"(c));
    return d;
}
__device__ __forceinline__ ull relu2(ull v) {
    float a, b; unpack2(v, a, b);
    return pack2(fmaxf(a, 0.f), fmaxf(b, 0.f));
}

// ---------------- index maps ------------------------------------------------
__device__ __forceinline__ int prior_to_loc(int i) {
    if (i < 5776) return i >> 2;
    if (i < 7942) return 1444 + (i - 5776) / 6;
    if (i < 8542) return 1805 + (i - 7942) / 6;
    if (i < 8692) return 1905 + (i - 8542) / 6;
    if (i < 8728) return 1930 + ((i - 8692) >> 2);
    return 1939;
}
__device__ __forceinline__ void loc_to_priors(int l, int& start, int& bpl) {
    if (l < 1444)      { start = 4 * l;                 bpl = 4; }
    else if (l < 1805) { start = 5776 + 6 * (l - 1444); bpl = 6; }
    else if (l < 1905) { start = 7942 + 6 * (l - 1805); bpl = 6; }
    else if (l < 1930) { start = 8542 + 6 * (l - 1905); bpl = 6; }
    else               { start = 8692 + 4 * (l - 1930); bpl = 4; }
}
__device__ __forceinline__ bool better(float a, int ia, float b, int ib) {
    return a > b || (a == b && ia < ib);
}
__device__ __forceinline__ void insert3(float v, int i,
                                        float& v0, int& i0, float& v1, int& i1,
                                        float& v2, int& i2) {
    if (better(v, i, v0, i0)) { v2 = v1; i2 = i1; v1 = v0; i1 = i0; v0 = v; i0 = i; }
    else if (better(v, i, v1, i1)) { v2 = v1; i2 = i1; v1 = v; i1 = i; }
    else if (better(v, i, v2, i2)) { v2 = v; i2 = i; }
}

// block-redundant top-3 locations of batch b -> prior index of rank j.
// 512-thread version; scratch needs 512*6 floats.
__device__ __forceinline__ int block_topk512(const float* __restrict__ z_depth,
                                             int b, int j, float* scratch) {
    const int tid = threadIdx.x;
    float (*sv)[3] = (float(*)[3])scratch;
    int   (*si)[3] = (int(*)[3])(scratch + 512 * 3);

    float v0 = -INFINITY, v1 = -INFINITY, v2 = -INFINITY;
    int   i0 = 0x7fffffff, i1 = 0x7fffffff, i2 = 0x7fffffff;
    const float4* __restrict__ zd4 =
        reinterpret_cast<const float4*>(z_depth + b * NLOC);
    for (int i = tid; i < NLOC / 4; i += 512) {
        const float4 v = __ldg(zd4 + i);
        insert3(v.x, 4 * i + 0, v0, i0, v1, i1, v2, i2);
        insert3(v.y, 4 * i + 1, v0, i0, v1, i1, v2, i2);
        insert3(v.z, 4 * i + 2, v0, i0, v1, i1, v2, i2);
        insert3(v.w, 4 * i + 3, v0, i0, v1, i1, v2, i2);
    }
    sv[tid][0] = v0; sv[tid][1] = v1; sv[tid][2] = v2;
    si[tid][0] = i0; si[tid][1] = i1; si[tid][2] = i2;
    __syncthreads();
    for (int s = 256; s > 0; s >>= 1) {
        if (tid < s) {
            #pragma unroll
            for (int q = 0; q < 3; q++)
                insert3(sv[tid + s][q], si[tid + s][q], v0, i0, v1, i1, v2, i2);
            sv[tid][0] = v0; sv[tid][1] = v1; sv[tid][2] = v2;
            si[tid][0] = i0; si[tid][1] = i1; si[tid][2] = i2;
        }
        __syncthreads();
    }
    __shared__ int s_ord;
    if (tid == 0) {
        int ranks[3] = { i0, i1, i2 };
        int ord = -1, cnt = 0;
        #pragma unroll
        for (int r = 0; r < 3; r++) {
            int start, bpl;
            loc_to_priors(ranks[r], start, bpl);
            if (ord < 0 && j < cnt + bpl) ord = start + (j - cnt);
            cnt += bpl;
        }
        s_ord = ord;
    }
    __syncthreads();
    return s_ord;
}

// ---------------------------------------------------------------------------
// 512-thread quadrant-pair deconv layer (R12 mapping: o = tid % CO, so a
// warp shares one (y,x) pixel -> smem broadcast reads, conflict-free stores).
// CO*H*XS must equal 512. PX = W/XS input pixels per thread.
// out[o, 2y+a, 2x+b] = bias[o] + sum_c in[c,y,x] * W[c,o,a,b]
// ---------------------------------------------------------------------------
template<int CI, int CO, int H, int W, int XS>
__device__ __forceinline__ void dlayer512(const float* __restrict__ in,
                                          float* __restrict__ out,
                                          const float* __restrict__ Wt,
                                          const float* __restrict__ bias)
{
    static_assert(CO * H * XS == 512, "thread mapping");
    constexpr int HW = H * W;
    constexpr int PX = W / XS;
    const int o   = threadIdx.x % CO;
    const int rem = threadIdx.x / CO;
    const int y   = rem % H;
    const int x0  = (rem / H) * PX;
    const ulonglong2* __restrict__ Wq = reinterpret_cast<const ulonglong2*>(Wt);
    const float bo = __ldg(bias + o);
    const ull bb = pack2(bo, bo);

    ull a01[PX], a23[PX];
    #pragma unroll
    for (int p = 0; p < PX; p++) { a01[p] = bb; a23[p] = bb; }

    const float* ip = in + y * W + x0;
    #pragma unroll 4
    for (int c = 0; c < CI; c++) {
        const ulonglong2 wq = __ldg(Wq + c * CO + o);   // (w0w1 | w2w3)
        if constexpr (PX == 1) {
            const float iv = ip[c * HW];
            const ull d = pack2(iv, iv);
            a01[0] = ffma2(d, wq.x, a01[0]);
            a23[0] = ffma2(d, wq.y, a23[0]);
        } else {
            const ull* __restrict__ ivp = reinterpret_cast<const ull*>(ip + c * HW);
            #pragma unroll
            for (int pp = 0; pp < PX / 2; pp++) {
                float i0, i1; unpack2(ivp[pp], i0, i1);
                const ull d0 = pack2(i0, i0);
                const ull d1 = pack2(i1, i1);
                a01[2 * pp]     = ffma2(d0, wq.x, a01[2 * pp]);
                a23[2 * pp]     = ffma2(d0, wq.y, a23[2 * pp]);
                a01[2 * pp + 1] = ffma2(d1, wq.x, a01[2 * pp + 1]);
                a23[2 * pp + 1] = ffma2(d1, wq.y, a23[2 * pp + 1]);
            }
        }
    }
    ull* r0 = reinterpret_cast<ull*>(out + (o * 2 * H + 2 * y) * (2 * W));
    ull* r1 = reinterpret_cast<ull*>(out + (o * 2 * H + 2 * y + 1) * (2 * W));
    #pragma unroll
    for (int p = 0; p < PX; p++) {
        r0[x0 + p] = relu2(a01[p]);
        r1[x0 + p] = relu2(a23[p]);
    }
}

// ---------------------------------------------------------------------------
// Decode kernel: topk + present-skip + L0..L5, one block per object, 512 thr.
// __launch_bounds__(512, 2): cap regs so TWO blocks co-reside per SM
// (2 x 96 KB smem fits the 227 KB carveout) -> the 12 blocks beyond 148 SMs
// interleave instead of serializing a full second wave.
// ---------------------------------------------------------------------------
__global__ void __launch_bounds__(512, 2) decode_kernel(
    const float* __restrict__ z_depth,
    const float* __restrict__ z_what,
    const int*   __restrict__ z_present,
    const float* __restrict__ W0, const float* __restrict__ b0,
    const float* __restrict__ W1, const float* __restrict__ b1,
    const float* __restrict__ W2, const float* __restrict__ b2,
    const float* __restrict__ W3, const float* __restrict__ b3,
    const float* __restrict__ W4, const float* __restrict__ b4,
    const float* __restrict__ W5, const float* __restrict__ b5)
{
    extern __shared__ __align__(16) float sm[];
    float* bufA = sm;           // up to 8192 floats
    float* bufB = sm + 8192;    // up to 16384 floats

    const int m = blockIdx.x;
    const int b = m / TOPK;
    const int j = m % TOPK;
    const int tid = threadIdx.x;

    const int ord = block_topk512(z_depth, b, j, bufB);
    if (tid == 0) g_order[m] = ord;

    // present-skip: composite never reads texels of non-present objects
    if (__ldg(z_present + b * NPRI + ord) != 1) return;

    const int loc = prior_to_loc(ord);
    const float* src = z_what + (size_t)(b * NLOC + loc) * ZWHAT;
    if (tid < ZWHAT) bufA[tid] = src[tid];
    __syncthreads();

    // ---- L0: 64 -> 256 ch, 1x1 -> 2x2 (threads 0..255) ----
    if (tid < 256) {
        const int o = tid;
        const ulonglong2* __restrict__ W0q = reinterpret_cast<const ulonglong2*>(W0);
        const float bo = __ldg(b0 + o);
        ull acc01 = pack2(bo, bo), acc23 = acc01;
        #pragma unroll 8
        for (int c = 0; c < 64; c++) {
            const ulonglong2 wq = __ldg(W0q + c * 256 + o);
            const ull ivd = pack2(bufA[c], bufA[c]);
            acc01 = ffma2(ivd, wq.x, acc01);
            acc23 = ffma2(ivd, wq.y, acc23);
        }
        ull* ob = reinterpret_cast<ull*>(bufB) + o * 2;
        ob[0] = relu2(acc01);   // [o][0][0..1]
        ob[1] = relu2(acc23);   // [o][1][0..1]
    }
    __syncthreads();

    dlayer512<256, 128,  2,  2, 2>(bufB, bufA, W1, b1); __syncthreads(); // 128x4x4
    dlayer512<128,  64,  4,  4, 2>(bufA, bufB, W2, b2); __syncthreads(); // 64x8x8
    dlayer512< 64,  32,  8,  8, 2>(bufB, bufA, W3, b3); __syncthreads(); // 32x16x16
    dlayer512< 32,  16, 16, 16, 2>(bufA, bufB, W4, b4); __syncthreads(); // 16x32x32

    // stage W5+b5 into bufA (free after L4 consumed it)
    if (tid < 192) bufA[tid] = __ldg(W5 + tid);
    if (tid < 3)   bufA[192 + tid] = __ldg(b5 + tid);
    __syncthreads();

    // ---- L5: 16 -> 3 ch, sigmoid, CPAD texels; 2 src px per thread ----
    {
        const int pbase = tid * 2;       // 0..1022
        const int sy = pbase >> 5;       // src row (32x32)
        const int sx = pbase & 31;       // src col (even)
        const ulonglong2* __restrict__ w5u =
            reinterpret_cast<const ulonglong2*>(bufA);
        ull a01[3][2], a23[3][2];
        #pragma unroll
        for (int o = 0; o < 3; o++) {
            const ull bb = pack2(bufA[192 + o], bufA[192 + o]);
            a01[o][0] = bb; a01[o][1] = bb;
            a23[o][0] = bb; a23[o][1] = bb;
        }
        #pragma unroll 4
        for (int c = 0; c < 16; c++) {
            const ull iv2 = *reinterpret_cast<const ull*>(bufB + c * 1024 + pbase);
            float i0, i1; unpack2(iv2, i0, i1);
            const ull d0 = pack2(i0, i0);
            const ull d1 = pack2(i1, i1);
            #pragma unroll
            for (int o = 0; o < 3; o++) {
                const ulonglong2 wq = w5u[c * 3 + o];
                a01[o][0] = ffma2(d0, wq.x, a01[o][0]);
                a23[o][0] = ffma2(d0, wq.y, a23[o][0]);
                a01[o][1] = ffma2(d1, wq.x, a01[o][1]);
                a23[o][1] = ffma2(d1, wq.y, a23[o][1]);
            }
        }
        float4* g4 = reinterpret_cast<float4*>(g_decoded) + (size_t)m * DS * DS;
        #pragma unroll
        for (int px = 0; px < 2; px++) {
            float rr[3][4];
            #pragma unroll
            for (int o = 0; o < 3; o++) {
                float v00, v01, v10, v11;
                unpack2(a01[o][px], v00, v01);
                unpack2(a23[o][px], v10, v11);
                rr[o][0] = 1.0f / (1.0f + __expf(-v00));
                rr[o][1] = 1.0f / (1.0f + __expf(-v01));
                rr[o][2] = 1.0f / (1.0f + __expf(-v10));
                rr[o][3] = 1.0f / (1.0f + __expf(-v11));
            }
            const int col0 = 2 * (sx + px);
            g4[(2 * sy) * DS + col0]         = make_float4(rr[0][0], rr[1][0], rr[2][0], 0.f);
            g4[(2 * sy) * DS + col0 + 1]     = make_float4(rr[0][1], rr[1][1], rr[2][1], 0.f);
            g4[(2 * sy + 1) * DS + col0]     = make_float4(rr[0][2], rr[1][2], rr[2][2], 0.f);
            g4[(2 * sy + 1) * DS + col0 + 1] = make_float4(rr[0][3], rr[1][3], rr[2][3], 0.f);
        }
    }
}

// ---------------------------------------------------------------------------
// Composite: fused STN + depth-ordered first-nonzero (unchanged, stable).
// ---------------------------------------------------------------------------
__global__ void __launch_bounds__(256) composite_kernel(
    const float* __restrict__ z_where,
    const int*   __restrict__ z_present,
    float* __restrict__ out)
{
    const int b = blockIdx.y;
    const int tx0 = (blockIdx.x % NTX) * TILE;
    const int ty0 = (blockIdx.x / NTX) * TILE;

    __shared__ float s_sx[TOPK], s_ox[TOPK], s_sy[TOPK], s_oy[TOPK];
    __shared__ int   s_flag[TOPK];
    __shared__ int   s_list[TOPK];
    __shared__ int   s_nc;

    const int tid = threadIdx.x;
    if (tid < TOPK) {
        const int ord = g_order[b * TOPK + tid];
        const float* zw = z_where + (size_t)(b * NPRI + ord) * 4;
        const float cx = zw[0], cy = zw[1];
        const float w = zw[2] + 1e-6f, h = zw[3] + 1e-6f;
        const float half = (float)DS * 0.5f;
        const float xsn = half / w;
        const float ysn = half / h;
        const float sx = xsn * (2.0f / (float)IMG);
        const float ox = half - 0.5f
                         + xsn * ((1.0f / (float)IMG - 1.0f) - (2.0f * cx - 1.0f));
        const float sy = ysn * (2.0f / (float)IMG);
        const float oy = half - 0.5f
                         + ysn * ((1.0f / (float)IMG - 1.0f) - (2.0f * cy - 1.0f));
        s_sx[tid] = sx; s_ox[tid] = ox; s_sy[tid] = sy; s_oy[tid] = oy;
        const float ix_lo = fmaf((float)tx0, sx, ox);
        const float ix_hi = fmaf((float)(tx0 + TILE - 1), sx, ox);
        const float iy_lo = fmaf((float)ty0, sy, oy);
        const float iy_hi = fmaf((float)(ty0 + TILE - 1), sy, oy);
        const bool pres = (z_present[b * NPRI + ord] == 1);
        s_flag[tid] = (pres &&
                       ix_hi >= -1.01f && ix_lo < 64.01f &&
                       iy_hi >= -1.01f && iy_lo < 64.01f) ? 1 : 0;
    }
    __syncthreads();
    if (tid == 0) {
        int nc = 0;
        #pragma unroll
        for (int k = 0; k < TOPK; k++)
            if (s_flag[k]) s_list[nc++] = k;
        s_nc = nc;
    }
    __syncthreads();

    const int x = tx0 + (tid % TILE);
    const int y = ty0 + (tid / TILE);
    if (x >= IMG || y >= IMG) return;
    const float fx = (float)x, fy = (float)y;

    float r0 = 0.0f, r1 = 0.0f, r2 = 0.0f;
    int done = 0;
    const int nc = s_nc;

    for (int kk = 0; kk < nc; kk++) {
        const int k = s_list[kk];
        const float ix = fmaf(fx, s_sx[k], s_ox[k]);
        const float iy = fmaf(fy, s_sy[k], s_oy[k]);
        const float ix0f = floorf(ix), iy0f = floorf(iy);
        if (!(ix0f >= -1.0f && ix0f <= 63.0f && iy0f >= -1.0f && iy0f <= 63.0f))
            continue;
        const float wx1 = ix - ix0f, wy1 = iy - iy0f;
        const float wx0 = 1.0f - wx1, wy0 = 1.0f - wy1;
        const int ix0 = (int)ix0f, iy0 = (int)iy0f;
        const bool vx0 = (ix0 >= 0), vx1 = (ix0 <= 62);
        const bool vy0 = (iy0 >= 0), vy1 = (iy0 <= 62);
        const float w00 = (vy0 && vx0) ? wy0 * wx0 : 0.0f;
        const float w01 = (vy0 && vx1) ? wy0 * wx1 : 0.0f;
        const float w10 = (vy1 && vx0) ? wy1 * wx0 : 0.0f;
        const float w11 = (vy1 && vx1) ? wy1 * wx1 : 0.0f;
        const int x0c = max(ix0, 0),     x1c = min(ix0 + 1, DS - 1);
        const int y0c = max(iy0, 0),     y1c = min(iy0 + 1, DS - 1);
        const int i00 = y0c * DS + x0c, i01 = y0c * DS + x1c;
        const int i10 = y1c * DS + x0c, i11 = y1c * DS + x1c;
        const float4* __restrict__ base = reinterpret_cast<const float4*>(g_decoded)
                                          + (size_t)(b * TOPK + k) * DS * DS;
        const float4 t00 = __ldg(base + i00);
        const float4 t01 = __ldg(base + i01);
        const float4 t10 = __ldg(base + i10);
        const float4 t11 = __ldg(base + i11);

        const float s0 = t00.x * w00 + t01.x * w01 + t10.x * w10 + t11.x * w11;
        const float s1 = t00.y * w00 + t01.y * w01 + t10.y * w10 + t11.y * w11;
        const float s2 = t00.z * w00 + t01.z * w01 + t10.z * w10 + t11.z * w11;

        if (!(done & 1) && s0 != 0.0f) { r0 = s0; done |= 1; }
        if (!(done & 2) && s1 != 0.0f) { r1 = s1; done |= 2; }
        if (!(done & 4) && s2 != 0.0f) { r2 = s2; done |= 4; }
        if (done == 7) break;
    }

    const size_t pix = (size_t)y * IMG + x;
    out[((size_t)(b * 3 + 0) * IMG * IMG) + pix] = r0;
    out[((size_t)(b * 3 + 1) * IMG * IMG) + pix] = r1;
    out[((size_t)(b * 3 + 2) * IMG * IMG) + pix] = r2;
}

// ---------------------------------------------------------------------------
extern "C" void kernel_launch(void* const* d_in, const int* in_sizes, int n_in,
                              void* d_out, int out_size)
{
    const float* z_what    = (const float*)d_in[0];
    const float* z_where   = (const float*)d_in[1];
    const int*   z_present = (const int*)  d_in[2];
    const float* z_depth   = (const float*)d_in[3];
    const float* W0 = (const float*)d_in[4];  const float* b0 = (const float*)d_in[5];
    const float* W1 = (const float*)d_in[6];  const float* b1 = (const float*)d_in[7];
    const float* W2 = (const float*)d_in[8];  const float* b2 = (const float*)d_in[9];
    const float* W3 = (const float*)d_in[10]; const float* b3 = (const float*)d_in[11];
    const float* W4 = (const float*)d_in[12]; const float* b4 = (const float*)d_in[13];
    const float* W5 = (const float*)d_in[14]; const float* b5 = (const float*)d_in[15];
    float* out = (float*)d_out;

    static bool attr_set = false;
    if (!attr_set) {
        cudaFuncSetAttribute(decode_kernel,
                             cudaFuncAttributeMaxDynamicSharedMemorySize,
                             (8192 + 16384) * sizeof(float));
        attr_set = true;
    }

    decode_kernel<<<NOBJ, 512, (8192 + 16384) * sizeof(float)>>>(
        z_depth, z_what, z_present,
        W0, b0, W1, b1, W2, b2, W3, b3, W4, b4, W5, b5);

    dim3 cgrid(NTX * NTX, BATCH);
    composite_kernel<<<cgrid, 256>>>(z_where, z_present, out);
}

// round 15
// speedup vs baseline: 1.2875x; 1.2875x over previous
#include <cuda_runtime.h>
#include <math.h>

#define NLOC 1940
#define NPRI 8732
#define BATCH 16
#define TOPK 10
#define NOBJ (BATCH*TOPK)
#define DS 64
#define IMG 300
#define ZWHAT 64
#define CPAD 4
#define TILE 16
#define NTX ((IMG + TILE - 1) / TILE)   // 19

typedef unsigned long long ull;

// ---------------- device scratch (no allocation allowed) -------------------
__device__ __align__(16) float g_decoded[NOBJ * CPAD * DS * DS];   // 10.5 MB
__device__ int   g_order[BATCH * TOPK];

// ---------------- f32x2 helpers --------------------------------------------
__device__ __forceinline__ ull pack2(float lo, float hi) {
    ull r; asm("mov.b64 %0, {%1, %2};" : "=l"(r) : "f"(lo), "f"(hi)); return r;
}
__device__ __forceinline__ void unpack2(ull v, float& a, float& b) {
    asm("mov.b64 {%0, %1}, %2;" : "=f"(a), "=f"(b) : "l"(v));
}
__device__ __forceinline__ ull ffma2(ull a, ull b, ull c) {
    ull d; asm("fma.rn.f32x2 %0, %1, %2, %3;" : "=l"(d) : "l"(a), "l"(b), "l"(c));
    return d;
}
__device__ __forceinline__ ull relu2(ull v) {
    float a, b; unpack2(v, a, b);
    return pack2(fmaxf(a, 0.f), fmaxf(b, 0.f));
}

// ---------------- index maps ------------------------------------------------
__device__ __forceinline__ int prior_to_loc(int i) {
    if (i < 5776) return i >> 2;
    if (i < 7942) return 1444 + (i - 5776) / 6;
    if (i < 8542) return 1805 + (i - 7942) / 6;
    if (i < 8692) return 1905 + (i - 8542) / 6;
    if (i < 8728) return 1930 + ((i - 8692) >> 2);
    return 1939;
}
__device__ __forceinline__ void loc_to_priors(int l, int& start, int& bpl) {
    if (l < 1444)      { start = 4 * l;                 bpl = 4; }
    else if (l < 1805) { start = 5776 + 6 * (l - 1444); bpl = 6; }
    else if (l < 1905) { start = 7942 + 6 * (l - 1805); bpl = 6; }
    else if (l < 1930) { start = 8542 + 6 * (l - 1905); bpl = 6; }
    else               { start = 8692 + 4 * (l - 1930); bpl = 4; }
}
__device__ __forceinline__ bool better(float a, int ia, float b, int ib) {
    return a > b || (a == b && ia < ib);
}
__device__ __forceinline__ void insert3(float v, int i,
                                        float& v0, int& i0, float& v1, int& i1,
                                        float& v2, int& i2) {
    if (better(v, i, v0, i0)) { v2 = v1; i2 = i1; v1 = v0; i1 = i0; v0 = v; i0 = i; }
    else if (better(v, i, v1, i1)) { v2 = v1; i2 = i1; v1 = v; i1 = i; }
    else if (better(v, i, v2, i2)) { v2 = v; i2 = i; }
}

// block-redundant top-3 locations of batch b -> prior index of rank j.
// 512-thread version; scratch needs 512*6 floats.
__device__ __forceinline__ int block_topk512(const float* __restrict__ z_depth,
                                             int b, int j, float* scratch) {
    const int tid = threadIdx.x;
    float (*sv)[3] = (float(*)[3])scratch;
    int   (*si)[3] = (int(*)[3])(scratch + 512 * 3);

    float v0 = -INFINITY, v1 = -INFINITY, v2 = -INFINITY;
    int   i0 = 0x7fffffff, i1 = 0x7fffffff, i2 = 0x7fffffff;
    const float4* __restrict__ zd4 =
        reinterpret_cast<const float4*>(z_depth + b * NLOC);
    for (int i = tid; i < NLOC / 4; i += 512) {
        const float4 v = __ldg(zd4 + i);
        insert3(v.x, 4 * i + 0, v0, i0, v1, i1, v2, i2);
        insert3(v.y, 4 * i + 1, v0, i0, v1, i1, v2, i2);
        insert3(v.z, 4 * i + 2, v0, i0, v1, i1, v2, i2);
        insert3(v.w, 4 * i + 3, v0, i0, v1, i1, v2, i2);
    }
    sv[tid][0] = v0; sv[tid][1] = v1; sv[tid][2] = v2;
    si[tid][0] = i0; si[tid][1] = i1; si[tid][2] = i2;
    __syncthreads();
    for (int s = 256; s > 0; s >>= 1) {
        if (tid < s) {
            #pragma unroll
            for (int q = 0; q < 3; q++)
                insert3(sv[tid + s][q], si[tid + s][q], v0, i0, v1, i1, v2, i2);
            sv[tid][0] = v0; sv[tid][1] = v1; sv[tid][2] = v2;
            si[tid][0] = i0; si[tid][1] = i1; si[tid][2] = i2;
        }
        __syncthreads();
    }
    __shared__ int s_ord;
    if (tid == 0) {
        int ranks[3] = { i0, i1, i2 };
        int ord = -1, cnt = 0;
        #pragma unroll
        for (int r = 0; r < 3; r++) {
            int start, bpl;
            loc_to_priors(ranks[r], start, bpl);
            if (ord < 0 && j < cnt + bpl) ord = start + (j - cnt);
            cnt += bpl;
        }
        s_ord = ord;
    }
    __syncthreads();
    return s_ord;
}

// ---------------------------------------------------------------------------
// 512-thread quadrant-pair deconv layer with DUPLICATED-activation input:
// input smem holds each value as an 8-byte (v,v) pair -> FFMA2 multiplicand
// is a single LDS.64, zero pack/unpack MOVs in the inner loop.
// R12 mapping (o = tid % CO): warp shares (y,x) -> broadcast reads.
// DUPOUT: write output duplicated (for next dup layer) or normal (for L5).
// out[o, 2y+a, 2x+b] = bias[o] + sum_c in[c,y,x] * W[c,o,a,b]
// ---------------------------------------------------------------------------
template<int CI, int CO, int H, int W, int XS, bool DUPOUT>
__device__ __forceinline__ void dlayer512(const float* __restrict__ in,
                                          float* __restrict__ out,
                                          const float* __restrict__ Wt,
                                          const float* __restrict__ bias)
{
    static_assert(CO * H * XS == 512, "thread mapping");
    constexpr int HW = H * W;
    constexpr int PX = W / XS;
    const int o   = threadIdx.x % CO;
    const int rem = threadIdx.x / CO;
    const int y   = rem % H;
    const int x0  = (rem / H) * PX;
    const ulonglong2* __restrict__ Wq = reinterpret_cast<const ulonglong2*>(Wt);
    const float bo = __ldg(bias + o);
    const ull bb = pack2(bo, bo);

    ull a01[PX], a23[PX];
    #pragma unroll
    for (int p = 0; p < PX; p++) { a01[p] = bb; a23[p] = bb; }

    const ull* __restrict__ ivd = reinterpret_cast<const ull*>(in);
    const int ibase = y * W + x0;
    #pragma unroll 4
    for (int c = 0; c < CI; c++) {
        const ulonglong2 wq = __ldg(Wq + c * CO + o);   // (w0w1 | w2w3)
        #pragma unroll
        for (int p = 0; p < PX; p++) {
            const ull d = ivd[c * HW + ibase + p];      // (v,v) duplicated
            a01[p] = ffma2(d, wq.x, a01[p]);
            a23[p] = ffma2(d, wq.y, a23[p]);
        }
    }
    if (DUPOUT) {
        // duplicated output: value idx (o*2H+ry)*2W + rx, stored as (v,v)
        ull* o0 = reinterpret_cast<ull*>(out) + (o * 2 * H + 2 * y) * (2 * W);
        ull* o1 = o0 + 2 * W;
        #pragma unroll
        for (int p = 0; p < PX; p++) {
            float va, vb;
            unpack2(a01[p], va, vb);
            va = fmaxf(va, 0.f); vb = fmaxf(vb, 0.f);
            o0[2 * (x0 + p)]     = pack2(va, va);
            o0[2 * (x0 + p) + 1] = pack2(vb, vb);
            unpack2(a23[p], va, vb);
            va = fmaxf(va, 0.f); vb = fmaxf(vb, 0.f);
            o1[2 * (x0 + p)]     = pack2(va, va);
            o1[2 * (x0 + p) + 1] = pack2(vb, vb);
        }
    } else {
        ull* r0 = reinterpret_cast<ull*>(out + (o * 2 * H + 2 * y) * (2 * W));
        ull* r1 = reinterpret_cast<ull*>(out + (o * 2 * H + 2 * y + 1) * (2 * W));
        #pragma unroll
        for (int p = 0; p < PX; p++) {
            r0[x0 + p] = relu2(a01[p]);
            r1[x0 + p] = relu2(a23[p]);
        }
    }
}

// ---------------------------------------------------------------------------
// Decode kernel: topk + present-skip + L0..L5, one block per object, 512 thr.
// bufA/bufB are 16384 floats each (128 KB total dynamic smem, 1 block/SM).
// Activations for L0..L3 outputs live DUPLICATED; L4 output normal for L5.
// ---------------------------------------------------------------------------
__global__ void __launch_bounds__(512, 1) decode_kernel(
    const float* __restrict__ z_depth,
    const float* __restrict__ z_what,
    const int*   __restrict__ z_present,
    const float* __restrict__ W0, const float* __restrict__ b0,
    const float* __restrict__ W1, const float* __restrict__ b1,
    const float* __restrict__ W2, const float* __restrict__ b2,
    const float* __restrict__ W3, const float* __restrict__ b3,
    const float* __restrict__ W4, const float* __restrict__ b4,
    const float* __restrict__ W5, const float* __restrict__ b5)
{
    extern __shared__ __align__(16) float sm[];
    float* bufA = sm;            // 16384 floats
    float* bufB = sm + 16384;    // 16384 floats

    const int m = blockIdx.x;
    const int b = m / TOPK;
    const int j = m % TOPK;
    const int tid = threadIdx.x;

    const int ord = block_topk512(z_depth, b, j, bufB);
    if (tid == 0) g_order[m] = ord;

    // present-skip: composite never reads texels of non-present objects
    if (__ldg(z_present + b * NPRI + ord) != 1) return;

    // gather z_what duplicated into bufA
    const int loc = prior_to_loc(ord);
    const float* src = z_what + (size_t)(b * NLOC + loc) * ZWHAT;
    if (tid < ZWHAT) {
        const float v = src[tid];
        reinterpret_cast<ull*>(bufA)[tid] = pack2(v, v);
    }
    __syncthreads();

    // ---- L0: 64 -> 256 ch, 1x1 -> 2x2 (threads 0..255), dup in & out ----
    if (tid < 256) {
        const int o = tid;
        const ulonglong2* __restrict__ W0q = reinterpret_cast<const ulonglong2*>(W0);
        const ull* __restrict__ zwd = reinterpret_cast<const ull*>(bufA);
        const float bo = __ldg(b0 + o);
        ull acc01 = pack2(bo, bo), acc23 = acc01;
        #pragma unroll 8
        for (int c = 0; c < 64; c++) {
            const ulonglong2 wq = __ldg(W0q + c * 256 + o);
            const ull d = zwd[c];
            acc01 = ffma2(d, wq.x, acc01);
            acc23 = ffma2(d, wq.y, acc23);
        }
        // duplicated output: [o][a][b] -> ull idx o*4 + a*2 + b
        ull* ob = reinterpret_cast<ull*>(bufB) + o * 4;
        float va, vb;
        unpack2(acc01, va, vb);
        va = fmaxf(va, 0.f); vb = fmaxf(vb, 0.f);
        ob[0] = pack2(va, va); ob[1] = pack2(vb, vb);
        unpack2(acc23, va, vb);
        va = fmaxf(va, 0.f); vb = fmaxf(vb, 0.f);
        ob[2] = pack2(va, va); ob[3] = pack2(vb, vb);
    }
    __syncthreads();

    dlayer512<256, 128,  2,  2, 2, true >(bufB, bufA, W1, b1); __syncthreads(); // 128x4x4 dup
    dlayer512<128,  64,  4,  4, 2, true >(bufA, bufB, W2, b2); __syncthreads(); // 64x8x8 dup
    dlayer512< 64,  32,  8,  8, 2, true >(bufB, bufA, W3, b3); __syncthreads(); // 32x16x16 dup
    dlayer512< 32,  16, 16, 16, 2, false>(bufA, bufB, W4, b4); __syncthreads(); // 16x32x32 normal

    // stage W5+b5 into bufA (free after L4 consumed it)
    if (tid < 192) bufA[tid] = __ldg(W5 + tid);
    if (tid < 3)   bufA[192 + tid] = __ldg(b5 + tid);
    __syncthreads();

    // ---- L5: 16 -> 3 ch, sigmoid, CPAD texels; 2 src px per thread ----
    {
        const int pbase = tid * 2;       // 0..1022
        const int sy = pbase >> 5;       // src row (32x32)
        const int sx = pbase & 31;       // src col (even)
        const ulonglong2* __restrict__ w5u =
            reinterpret_cast<const ulonglong2*>(bufA);
        ull a01[3][2], a23[3][2];
        #pragma unroll
        for (int o = 0; o < 3; o++) {
            const ull bb = pack2(bufA[192 + o], bufA[192 + o]);
            a01[o][0] = bb; a01[o][1] = bb;
            a23[o][0] = bb; a23[o][1] = bb;
        }
        #pragma unroll 4
        for (int c = 0; c < 16; c++) {
            const ull iv2 = *reinterpret_cast<const ull*>(bufB + c * 1024 + pbase);
            float i0, i1; unpack2(iv2, i0, i1);
            const ull d0 = pack2(i0, i0);
            const ull d1 = pack2(i1, i1);
            #pragma unroll
            for (int o = 0; o < 3; o++) {
                const ulonglong2 wq = w5u[c * 3 + o];
                a01[o][0] = ffma2(d0, wq.x, a01[o][0]);
                a23[o][0] = ffma2(d0, wq.y, a23[o][0]);
                a01[o][1] = ffma2(d1, wq.x, a01[o][1]);
                a23[o][1] = ffma2(d1, wq.y, a23[o][1]);
            }
        }
        float4* g4 = reinterpret_cast<float4*>(g_decoded) + (size_t)m * DS * DS;
        #pragma unroll
        for (int px = 0; px < 2; px++) {
            float rr[3][4];
            #pragma unroll
            for (int o = 0; o < 3; o++) {
                float v00, v01, v10, v11;
                unpack2(a01[o][px], v00, v01);
                unpack2(a23[o][px], v10, v11);
                rr[o][0] = 1.0f / (1.0f + __expf(-v00));
                rr[o][1] = 1.0f / (1.0f + __expf(-v01));
                rr[o][2] = 1.0f / (1.0f + __expf(-v10));
                rr[o][3] = 1.0f / (1.0f + __expf(-v11));
            }
            const int col0 = 2 * (sx + px);
            g4[(2 * sy) * DS + col0]         = make_float4(rr[0][0], rr[1][0], rr[2][0], 0.f);
            g4[(2 * sy) * DS + col0 + 1]     = make_float4(rr[0][1], rr[1][1], rr[2][1], 0.f);
            g4[(2 * sy + 1) * DS + col0]     = make_float4(rr[0][2], rr[1][2], rr[2][2], 0.f);
            g4[(2 * sy + 1) * DS + col0 + 1] = make_float4(rr[0][3], rr[1][3], rr[2][3], 0.f);
        }
    }
}

// ---------------------------------------------------------------------------
// Composite: fused STN + depth-ordered first-nonzero (unchanged, stable).
// ---------------------------------------------------------------------------
__global__ void __launch_bounds__(256) composite_kernel(
    const float* __restrict__ z_where,
    const int*   __restrict__ z_present,
    float* __restrict__ out)
{
    const int b = blockIdx.y;
    const int tx0 = (blockIdx.x % NTX) * TILE;
    const int ty0 = (blockIdx.x / NTX) * TILE;

    __shared__ float s_sx[TOPK], s_ox[TOPK], s_sy[TOPK], s_oy[TOPK];
    __shared__ int   s_flag[TOPK];
    __shared__ int   s_list[TOPK];
    __shared__ int   s_nc;

    const int tid = threadIdx.x;
    if (tid < TOPK) {
        const int ord = g_order[b * TOPK + tid];
        const float* zw = z_where + (size_t)(b * NPRI + ord) * 4;
        const float cx = zw[0], cy = zw[1];
        const float w = zw[2] + 1e-6f, h = zw[3] + 1e-6f;
        const float half = (float)DS * 0.5f;
        const float xsn = half / w;
        const float ysn = half / h;
        const float sx = xsn * (2.0f / (float)IMG);
        const float ox = half - 0.5f
                         + xsn * ((1.0f / (float)IMG - 1.0f) - (2.0f * cx - 1.0f));
        const float sy = ysn * (2.0f / (float)IMG);
        const float oy = half - 0.5f
                         + ysn * ((1.0f / (float)IMG - 1.0f) - (2.0f * cy - 1.0f));
        s_sx[tid] = sx; s_ox[tid] = ox; s_sy[tid] = sy; s_oy[tid] = oy;
        const float ix_lo = fmaf((float)tx0, sx, ox);
        const float ix_hi = fmaf((float)(tx0 + TILE - 1), sx, ox);
        const float iy_lo = fmaf((float)ty0, sy, oy);
        const float iy_hi = fmaf((float)(ty0 + TILE - 1), sy, oy);
        const bool pres = (z_present[b * NPRI + ord] == 1);
        s_flag[tid] = (pres &&
                       ix_hi >= -1.01f && ix_lo < 64.01f &&
                       iy_hi >= -1.01f && iy_lo < 64.01f) ? 1 : 0;
    }
    __syncthreads();
    if (tid == 0) {
        int nc = 0;
        #pragma unroll
        for (int k = 0; k < TOPK; k++)
            if (s_flag[k]) s_list[nc++] = k;
        s_nc = nc;
    }
    __syncthreads();

    const int x = tx0 + (tid % TILE);
    const int y = ty0 + (tid / TILE);
    if (x >= IMG || y >= IMG) return;
    const float fx = (float)x, fy = (float)y;

    float r0 = 0.0f, r1 = 0.0f, r2 = 0.0f;
    int done = 0;
    const int nc = s_nc;

    for (int kk = 0; kk < nc; kk++) {
        const int k = s_list[kk];
        const float ix = fmaf(fx, s_sx[k], s_ox[k]);
        const float iy = fmaf(fy, s_sy[k], s_oy[k]);
        const float ix0f = floorf(ix), iy0f = floorf(iy);
        if (!(ix0f >= -1.0f && ix0f <= 63.0f && iy0f >= -1.0f && iy0f <= 63.0f))
            continue;
        const float wx1 = ix - ix0f, wy1 = iy - iy0f;
        const float wx0 = 1.0f - wx1, wy0 = 1.0f - wy1;
        const int ix0 = (int)ix0f, iy0 = (int)iy0f;
        const bool vx0 = (ix0 >= 0), vx1 = (ix0 <= 62);
        const bool vy0 = (iy0 >= 0), vy1 = (iy0 <= 62);
        const float w00 = (vy0 && vx0) ? wy0 * wx0 : 0.0f;
        const float w01 = (vy0 && vx1) ? wy0 * wx1 : 0.0f;
        const float w10 = (vy1 && vx0) ? wy1 * wx0 : 0.0f;
        const float w11 = (vy1 && vx1) ? wy1 * wx1 : 0.0f;
        const int x0c = max(ix0, 0),     x1c = min(ix0 + 1, DS - 1);
        const int y0c = max(iy0, 0),     y1c = min(iy0 + 1, DS - 1);
        const int i00 = y0c * DS + x0c, i01 = y0c * DS + x1c;
        const int i10 = y1c * DS + x0c, i11 = y1c * DS + x1c;
        const float4* __restrict__ base = reinterpret_cast<const float4*>(g_decoded)
                                          + (size_t)(b * TOPK + k) * DS * DS;
        const float4 t00 = __ldg(base + i00);
        const float4 t01 = __ldg(base + i01);
        const float4 t10 = __ldg(base + i10);
        const float4 t11 = __ldg(base + i11);

        const float s0 = t00.x * w00 + t01.x * w01 + t10.x * w10 + t11.x * w11;
        const float s1 = t00.y * w00 + t01.y * w01 + t10.y * w10 + t11.y * w11;
        const float s2 = t00.z * w00 + t01.z * w01 + t10.z * w10 + t11.z * w11;

        if (!(done & 1) && s0 != 0.0f) { r0 = s0; done |= 1; }
        if (!(done & 2) && s1 != 0.0f) { r1 = s1; done |= 2; }
        if (!(done & 4) && s2 != 0.0f) { r2 = s2; done |= 4; }
        if (done == 7) break;
    }

    const size_t pix = (size_t)y * IMG + x;
    out[((size_t)(b * 3 + 0) * IMG * IMG) + pix] = r0;
    out[((size_t)(b * 3 + 1) * IMG * IMG) + pix] = r1;
    out[((size_t)(b * 3 + 2) * IMG * IMG) + pix] = r2;
}

// ---------------------------------------------------------------------------
extern "C" void kernel_launch(void* const* d_in, const int* in_sizes, int n_in,
                              void* d_out, int out_size)
{
    const float* z_what    = (const float*)d_in[0];
    const float* z_where   = (const float*)d_in[1];
    const int*   z_present = (const int*)  d_in[2];
    const float* z_depth   = (const float*)d_in[3];
    const float* W0 = (const float*)d_in[4];  const float* b0 = (const float*)d_in[5];
    const float* W1 = (const float*)d_in[6];  const float* b1 = (const float*)d_in[7];
    const float* W2 = (const float*)d_in[8];  const float* b2 = (const float*)d_in[9];
    const float* W3 = (const float*)d_in[10]; const float* b3 = (const float*)d_in[11];
    const float* W4 = (const float*)d_in[12]; const float* b4 = (const float*)d_in[13];
    const float* W5 = (const float*)d_in[14]; const float* b5 = (const float*)d_in[15];
    float* out = (float*)d_out;

    static bool attr_set = false;
    if (!attr_set) {
        cudaFuncSetAttribute(decode_kernel,
                             cudaFuncAttributeMaxDynamicSharedMemorySize,
                             (16384 + 16384) * sizeof(float));
        attr_set = true;
    }

    decode_kernel<<<NOBJ, 512, (16384 + 16384) * sizeof(float)>>>(
        z_depth, z_what, z_present,
        W0, b0, W1, b1, W2, b2, W3, b3, W4, b4, W5, b5);

    dim3 cgrid(NTX * NTX, BATCH);
    composite_kernel<<<cgrid, 256>>>(z_where, z_present, out);
}